// round 6
// baseline (speedup 1.0000x reference)
#include <cuda_runtime.h>

// PBKDF2-toy, serial single-warp hash at the issue-slot floor. R6 change:
// the 32 off-critical-path F-xors per iteration are replaced by 8 STS.128
// spills of U to shared memory (issue ~1-2 each vs 32 LOP3 slots), and the
// 1000-way xor fold runs as a trailing parallel phase on 4 warps (~0.5us).
// All-lanes same-address stores (uniform values) avoid the C++ if -> BSSY
// divergence penalty. Harness dtype shims: float32 out, sniffed in (R3).

#define HASH_ITERS 1000
// 1000 U-states x 32 words, + 128 words for partial-xor scratch
#define SMEM_WORDS (HASH_ITERS * 32 + 128)

__device__ __forceinline__ unsigned load_byte(const void* p, int i) {
    int v = ((const int*)p)[i];
    if ((unsigned)v <= 255u) return (unsigned)v;   // int32 input
    return (unsigned)(int)__int_as_float(v);       // float32 input
}

__global__ void __launch_bounds__(128, 1)
Model_62955630625117_kernel(const void* __restrict__ pw_in,
                            const void* __restrict__ salt_in,
                            float* __restrict__ out) {
    extern __shared__ unsigned su[];

    if (threadIdx.x < 32) {
        // ---- Phase 1: serial hash chain (warp 0, all lanes uniform) ----
        unsigned c[16];   // (pw[j]*31) & 255, loop-invariant
        unsigned r[32];   // hash state U

        #pragma unroll
        for (int j = 0; j < 16; j++) {
            unsigned p = load_byte(pw_in, j);
            c[j] = (p * 31u) & 255u;
            r[j] = p;
        }
        #pragma unroll
        for (int j = 0; j < 16; j++) r[16 + j] = load_byte(salt_in, j);

        // First hmac message = salt(16) ++ block_num{0,0,0,1}
        r[0] = c[0];
        r[1] = c[1];
        r[2] = c[2];
        r[3] = (c[3] + 1u) & 255u;

        #pragma unroll
        for (int rd = 0; rd < 4; rd++) {
            #pragma unroll
            for (int i = 0; i < 32; i++)
                r[i] = (r[i] ^ (r[(i + 17) & 31] + r[(i + 11) & 31])) & 255u;
        }
        // spill U0
        #pragma unroll
        for (int q = 0; q < 8; q++)
            *(uint4*)(su + 4 * q) =
                make_uint4(r[4 * q], r[4 * q + 1], r[4 * q + 2], r[4 * q + 3]);

        // 999 chained iterations: U = hmac(pw, U); spill U.
        // Absorb collapse: r[j] = c[j] + r[16+j] (9-bit OK, mix LOP3 re-masks),
        // r[16+j] = old r[j] (order-2 swap; even unroll -> pure renaming).
        #pragma unroll 4
        for (int it = 1; it < HASH_ITERS; it++) {
            #pragma unroll
            for (int j = 0; j < 16; j++) {
                unsigned t = r[j];
                r[j] = c[j] + r[16 + j];
                r[16 + j] = t;
            }
            #pragma unroll
            for (int rd = 0; rd < 4; rd++) {
                #pragma unroll
                for (int i = 0; i < 32; i++)
                    r[i] = (r[i] ^ (r[(i + 17) & 31] + r[(i + 11) & 31])) & 255u;
            }
            unsigned* dst = su + it * 32;
            #pragma unroll
            for (int q = 0; q < 8; q++)
                *(uint4*)(dst + 4 * q) =
                    make_uint4(r[4 * q], r[4 * q + 1], r[4 * q + 2], r[4 * q + 3]);
        }
    }
    __syncthreads();

    // ---- Phase 2: parallel 1000-way xor fold (4 warps, coalesced) ----
    int col = threadIdx.x & 31;
    int sl  = threadIdx.x >> 5;        // slice 0..3
    unsigned acc = 0;
    #pragma unroll 4
    for (int t = sl; t < HASH_ITERS; t += 4)
        acc ^= su[t * 32 + col];
    su[HASH_ITERS * 32 + threadIdx.x] = acc;
    __syncthreads();

    if (threadIdx.x < 32) {
        unsigned f = su[HASH_ITERS * 32 + col]
                   ^ su[HASH_ITERS * 32 + 32 + col]
                   ^ su[HASH_ITERS * 32 + 64 + col]
                   ^ su[HASH_ITERS * 32 + 96 + col];
        out[col] = (float)f;
    }
}

extern "C" void kernel_launch(void* const* d_in, const int* in_sizes, int n_in,
                              void* d_out, int out_size) {
    const void* password = d_in[0];
    const void* salt     = (n_in >= 2) ? d_in[1] : (const void*)((const int*)d_in[0] + 16);
    float* out           = (float*)d_out;

    const size_t smem_bytes = SMEM_WORDS * sizeof(unsigned);   // ~125.5 KB
    cudaFuncSetAttribute(Model_62955630625117_kernel,
                         cudaFuncAttributeMaxDynamicSharedMemorySize,
                         (int)smem_bytes);
    Model_62955630625117_kernel<<<1, 128, smem_bytes>>>(password, salt, out);
}